// round 12
// baseline (speedup 1.0000x reference)
#include <cuda_runtime.h>

#define Bsz 32
#define Hh 480
#define Ww 640
#define HW (Hh*Ww)          // 307200 pixels per channel-plane
#define HW4 (HW/4)          // 76800 float4 per plane
#define TPB 256
#define PBLK (HW4/TPB)      // 300 blocks per image (both passes)

__device__ float d_part[Bsz * PBLK];   // per-block partial gray sums (overwritten each call)

__device__ __forceinline__ float clip01(float v) {
    return fminf(fmaxf(v, 0.0f), 1.0f);
}

__device__ __forceinline__ float rcp_approx(float x) {
    float r;
    asm("rcp.approx.f32 %0, %1;" : "=f"(r) : "f"(x));
    return r;
}

// Pass 1: per-block partial sum of gray(clip(x * bf)).  grid = (PBLK, B), block = 256.
// Default load policy: leave input resident in L2 for pass 2 (LIFO reuse).
__global__ void __launch_bounds__(TPB) gray_reduce(const float* __restrict__ x,
                                                   const float* __restrict__ bf) {
    const int b    = blockIdx.y;
    const int slot = blockIdx.x;
    const int g4   = slot * TPB + threadIdx.x;
    const float s  = bf[b];

    const float4* base = (const float4*)(x) + (size_t)b * 3 * HW4;
    float4 r4 = base[g4];
    float4 g4v = base[g4 + HW4];
    float4 b4 = base[g4 + 2 * HW4];

    float acc;
    {
        float r = clip01(r4.x * s), g = clip01(g4v.x * s), bb = clip01(b4.x * s);
        acc  = 0.299f * r + 0.587f * g + 0.114f * bb;
        r = clip01(r4.y * s); g = clip01(g4v.y * s); bb = clip01(b4.y * s);
        acc += 0.299f * r + 0.587f * g + 0.114f * bb;
        r = clip01(r4.z * s); g = clip01(g4v.z * s); bb = clip01(b4.z * s);
        acc += 0.299f * r + 0.587f * g + 0.114f * bb;
        r = clip01(r4.w * s); g = clip01(g4v.w * s); bb = clip01(b4.w * s);
        acc += 0.299f * r + 0.587f * g + 0.114f * bb;
    }

    for (int off = 16; off > 0; off >>= 1)
        acc += __shfl_down_sync(0xFFFFFFFF, acc, off);

    __shared__ float warp_part[TPB / 32];
    const int lane = threadIdx.x & 31;
    const int wid  = threadIdx.x >> 5;
    if (lane == 0) warp_part[wid] = acc;
    __syncthreads();
    if (wid == 0) {
        float v = (lane < TPB / 32) ? warp_part[lane] : 0.0f;
        for (int off = 4; off > 0; off >>= 1)
            v += __shfl_down_sync(0xFFFFFFFF, v, off);
        if (lane == 0) d_part[b * PBLK + slot] = v;
    }
}

__device__ __forceinline__ float fracf(float x) { return x - floorf(x); }

// One channel of branchless HSV reconstruction: ch = minc + cr * clamp(|frac(u)*6-3|-1, 0, 1)
__device__ __forceinline__ float hsv_ch(float u, float cr, float minc) {
    float t = fracf(u);
    float a = fabsf(fmaf(t, 6.0f, -3.0f)) - 1.0f;
    float w = fminf(fmaxf(a, 0.0f), 1.0f);
    return fmaf(cr, w, minc);
}

// Pass 2: fused transform, images in REVERSE order (LIFO L2 reuse).
// Loads: __ldcs (last use).  Stores: __stwt (write-through, no L2 allocation —
// keeps the still-needed input resident in L2).
__global__ void __launch_bounds__(TPB) color_xform(const float* __restrict__ x,
                            const float* __restrict__ bfv,
                            const float* __restrict__ cfv,
                            const float* __restrict__ sfv,
                            const float* __restrict__ hfv,
                            float* __restrict__ out) {
    const int blk  = blockIdx.x;                 // 0 .. B*PBLK-1
    const int b    = (Bsz - 1) - blk / PBLK;     // reversed image order
    const int slot = blk % PBLK;
    const int g4   = slot * TPB + threadIdx.x;

    const float4* ibase = (const float4*)(x) + (size_t)b * 3 * HW4;
    float4*       obase = (float4*)(out)     + (size_t)b * 3 * HW4;

    // Long-latency pixel loads first (overlap with partial re-reduction).
    float4 rv = __ldcs(ibase + g4);
    float4 gv = __ldcs(ibase + g4 + HW4);
    float4 bv = __ldcs(ibase + g4 + 2 * HW4);

    // Re-reduce the 300 per-block partials for this image (L2-hot, deterministic).
    const int t = threadIdx.x;
    float acc = d_part[b * PBLK + t];
    if (t < PBLK - TPB) acc += d_part[b * PBLK + t + TPB];
    for (int off = 16; off > 0; off >>= 1)
        acc += __shfl_down_sync(0xFFFFFFFF, acc, off);
    __shared__ float warp_part[TPB / 32];
    __shared__ float s_mean;
    const int lane = t & 31;
    const int wid  = t >> 5;
    if (lane == 0) warp_part[wid] = acc;
    __syncthreads();
    if (wid == 0) {
        float v = (lane < TPB / 32) ? warp_part[lane] : 0.0f;
        for (int off = 4; off > 0; off >>= 1)
            v += __shfl_down_sync(0xFFFFFFFF, v, off);
        if (lane == 0) s_mean = v * (1.0f / (float)HW);
    }
    __syncthreads();
    const float mean = s_mean;

    const float bf = bfv[b];
    const float cf = cfv[b];
    const float sf = sfv[b];
    const float hf = hfv[b];
    const float cm = (1.0f - cf) * mean;           // contrast blend constant
    // frac() is invariant to integer offsets: fold both %1.0 mods and the
    // per-channel hue offsets into single frac calls.
    const float hk_r = hf;                         // k=0  (== k=1 mod 1)
    const float hk_g = hf + (2.0f / 3.0f);
    const float hk_b = hf + (1.0f / 3.0f);

    float rr[4] = {rv.x, rv.y, rv.z, rv.w};
    float gg[4] = {gv.x, gv.y, gv.z, gv.w};
    float bb[4] = {bv.x, bv.y, bv.z, bv.w};

    #pragma unroll
    for (int k = 0; k < 4; k++) {
        float r  = clip01(rr[k] * bf);
        float g  = clip01(gg[k] * bf);
        float bl = clip01(bb[k] * bf);
        r  = clip01(fmaf(cf, r,  cm));
        g  = clip01(fmaf(cf, g,  cm));
        bl = clip01(fmaf(cf, bl, cm));
        float gray = 0.299f * r + 0.587f * g + 0.114f * bl;
        float sm = (1.0f - sf) * gray;
        r  = clip01(fmaf(sf, r,  sm));
        g  = clip01(fmaf(sf, g,  sm));
        bl = clip01(fmaf(sf, bl, sm));

        // HSV hue rotation:  v*s = cr,  v*(1-s) = minc  ->  ch = minc + cr*w_ch
        float maxc = fmaxf(r, fmaxf(g, bl));
        float minc = fminf(r, fminf(g, bl));
        float cr   = maxc - minc;
        float crd  = (cr == 0.0f) ? 1.0f : cr;
        float inv6 = rcp_approx(crd) * (1.0f / 6.0f);

        bool pr = (maxc == r);
        bool pg = (maxc == g) && !pr;
        float da   = pr ? g  : (pg ? bl : r);
        float db   = pr ? bl : (pg ? r  : g);
        float off6 = pr ? 0.0f : (pg ? (2.0f / 6.0f) : (4.0f / 6.0f));
        float hbase = fmaf(da - db, inv6, off6);

        rr[k] = hsv_ch(hbase + hk_r, cr, minc);
        gg[k] = hsv_ch(hbase + hk_g, cr, minc);
        bb[k] = hsv_ch(hbase + hk_b, cr, minc);
    }

    __stwt(obase + g4,           make_float4(rr[0], rr[1], rr[2], rr[3]));
    __stwt(obase + g4 + HW4,     make_float4(gg[0], gg[1], gg[2], gg[3]));
    __stwt(obase + g4 + 2 * HW4, make_float4(bb[0], bb[1], bb[2], bb[3]));
}

extern "C" void kernel_launch(void* const* d_in, const int* in_sizes, int n_in,
                              void* d_out, int out_size) {
    const float* x  = (const float*)d_in[0];
    const float* bf = (const float*)d_in[1];
    const float* cf = (const float*)d_in[2];
    const float* sf = (const float*)d_in[3];
    const float* hf = (const float*)d_in[4];
    float* out = (float*)d_out;

    gray_reduce<<<dim3(PBLK, Bsz), TPB>>>(x, bf);
    color_xform<<<Bsz * PBLK, TPB>>>(x, bf, cf, sf, hf, out);
}

// round 15
// speedup vs baseline: 1.0357x; 1.0357x over previous
#include <cuda_runtime.h>

#define Bsz 32
#define Hh 480
#define Ww 640
#define HW (Hh*Ww)          // 307200 pixels per channel-plane
#define HW8 (HW/8)          // 38400 8-float groups per plane
#define TPB 256
#define PBLK (HW8/TPB)      // 150 blocks per image (both passes)

__device__ float d_part[Bsz * PBLK];   // per-block partial gray sums (overwritten each call)

__device__ __forceinline__ float clip01(float v) {
    return fminf(fmaxf(v, 0.0f), 1.0f);
}

__device__ __forceinline__ float rcp_approx(float x) {
    float r;
    asm("rcp.approx.f32 %0, %1;" : "=f"(r) : "f"(x));
    return r;
}

struct f8 { float v[8]; };

__device__ __forceinline__ void unpack2(unsigned long long u, float& a, float& b) {
    asm("mov.b64 {%0,%1}, %2;" : "=f"(a), "=f"(b) : "l"(u));
}
__device__ __forceinline__ unsigned long long pack2(float a, float b) {
    unsigned long long u;
    asm("mov.b64 %0, {%1,%2};" : "=l"(u) : "f"(a), "f"(b));
    return u;
}

// 256-bit load, L2 evict-last (pin input in L2 for pass 2)
__device__ __forceinline__ f8 ld8_evict_last(const float* p) {
    unsigned long long x0, x1, x2, x3;
    asm("ld.global.nc.L2::evict_last.v4.b64 {%0,%1,%2,%3}, [%4];"
        : "=l"(x0), "=l"(x1), "=l"(x2), "=l"(x3) : "l"(p));
    f8 r;
    unpack2(x0, r.v[0], r.v[1]); unpack2(x1, r.v[2], r.v[3]);
    unpack2(x2, r.v[4], r.v[5]); unpack2(x3, r.v[6], r.v[7]);
    return r;
}

// 256-bit load, L2 evict-first (last use in pass 2)
__device__ __forceinline__ f8 ld8_evict_first(const float* p) {
    unsigned long long x0, x1, x2, x3;
    asm("ld.global.nc.L2::evict_first.v4.b64 {%0,%1,%2,%3}, [%4];"
        : "=l"(x0), "=l"(x1), "=l"(x2), "=l"(x3) : "l"(p));
    f8 r;
    unpack2(x0, r.v[0], r.v[1]); unpack2(x1, r.v[2], r.v[3]);
    unpack2(x2, r.v[4], r.v[5]); unpack2(x3, r.v[6], r.v[7]);
    return r;
}

// 256-bit streaming store
__device__ __forceinline__ void st8_cs(float* p, const float* s) {
    unsigned long long x0 = pack2(s[0], s[1]);
    unsigned long long x1 = pack2(s[2], s[3]);
    unsigned long long x2 = pack2(s[4], s[5]);
    unsigned long long x3 = pack2(s[6], s[7]);
    asm volatile("st.global.cs.v4.b64 [%0], {%1,%2,%3,%4};"
                 :: "l"(p), "l"(x0), "l"(x1), "l"(x2), "l"(x3) : "memory");
}

// Pass 1: per-block partial sum of gray(clip(x * bf)).  grid = (PBLK, B), block = 256.
// Loads carry L2::evict_last so input outlives pass-2's store allocations.
__global__ void __launch_bounds__(TPB) gray_reduce(const float* __restrict__ x,
                                                   const float* __restrict__ bf) {
    const int b    = blockIdx.y;
    const int slot = blockIdx.x;
    const int g8   = slot * TPB + threadIdx.x;
    const float s  = bf[b];

    const float* base = x + (size_t)b * 3 * HW + (size_t)g8 * 8;
    f8 R = ld8_evict_last(base);
    f8 G = ld8_evict_last(base + HW);
    f8 Bv = ld8_evict_last(base + 2 * HW);

    float acc = 0.0f;
    #pragma unroll
    for (int k = 0; k < 8; k++) {
        float r = clip01(R.v[k] * s), g = clip01(G.v[k] * s), bb = clip01(Bv.v[k] * s);
        acc += 0.299f * r + 0.587f * g + 0.114f * bb;
    }

    for (int off = 16; off > 0; off >>= 1)
        acc += __shfl_down_sync(0xFFFFFFFF, acc, off);

    __shared__ float warp_part[TPB / 32];
    const int lane = threadIdx.x & 31;
    const int wid  = threadIdx.x >> 5;
    if (lane == 0) warp_part[wid] = acc;
    __syncthreads();
    if (wid == 0) {
        float v = (lane < TPB / 32) ? warp_part[lane] : 0.0f;
        for (int off = 4; off > 0; off >>= 1)
            v += __shfl_down_sync(0xFFFFFFFF, v, off);
        if (lane == 0) d_part[b * PBLK + slot] = v;
    }
}

__device__ __forceinline__ float fracf(float x) { return x - floorf(x); }

// One channel of branchless HSV reconstruction: ch = minc + cr * clamp(|frac(u)*6-3|-1, 0, 1)
__device__ __forceinline__ float hsv_ch(float u, float cr, float minc) {
    float t = fracf(u);
    float a = fabsf(fmaf(t, 6.0f, -3.0f)) - 1.0f;
    float w = fminf(fmaxf(a, 0.0f), 1.0f);
    return fmaf(cr, w, minc);
}

// Pass 2: fused transform, images in REVERSE order (LIFO L2 reuse).
// Loads: 256-bit evict_first (last use).  Stores: 256-bit streaming.
__global__ void __launch_bounds__(TPB) color_xform(const float* __restrict__ x,
                            const float* __restrict__ bfv,
                            const float* __restrict__ cfv,
                            const float* __restrict__ sfv,
                            const float* __restrict__ hfv,
                            float* __restrict__ out) {
    const int blk  = blockIdx.x;                 // 0 .. B*PBLK-1
    const int b    = (Bsz - 1) - blk / PBLK;     // reversed image order
    const int slot = blk % PBLK;
    const int g8   = slot * TPB + threadIdx.x;

    const float* ibase = x   + (size_t)b * 3 * HW + (size_t)g8 * 8;
    float*       obase = out + (size_t)b * 3 * HW + (size_t)g8 * 8;

    // Long-latency pixel loads first (overlap with partial re-reduction).
    f8 R  = ld8_evict_first(ibase);
    f8 G  = ld8_evict_first(ibase + HW);
    f8 Bv = ld8_evict_first(ibase + 2 * HW);

    // Re-reduce the 150 per-block partials for this image (L2-hot, deterministic).
    const int t = threadIdx.x;
    float acc = (t < PBLK) ? d_part[b * PBLK + t] : 0.0f;
    for (int off = 16; off > 0; off >>= 1)
        acc += __shfl_down_sync(0xFFFFFFFF, acc, off);
    __shared__ float warp_part[TPB / 32];
    __shared__ float s_mean;
    const int lane = t & 31;
    const int wid  = t >> 5;
    if (lane == 0) warp_part[wid] = acc;
    __syncthreads();
    if (wid == 0) {
        float v = (lane < TPB / 32) ? warp_part[lane] : 0.0f;
        for (int off = 4; off > 0; off >>= 1)
            v += __shfl_down_sync(0xFFFFFFFF, v, off);
        if (lane == 0) s_mean = v * (1.0f / (float)HW);
    }
    __syncthreads();
    const float mean = s_mean;

    const float bf = bfv[b];
    const float cf = cfv[b];
    const float sf = sfv[b];
    const float hf = hfv[b];
    const float cm = (1.0f - cf) * mean;           // contrast blend constant
    const float hk_r = hf;                         // frac folds integer offsets
    const float hk_g = hf + (2.0f / 3.0f);
    const float hk_b = hf + (1.0f / 3.0f);

    #pragma unroll
    for (int k = 0; k < 8; k++) {
        float r  = clip01(R.v[k]  * bf);
        float g  = clip01(G.v[k]  * bf);
        float bl = clip01(Bv.v[k] * bf);
        r  = clip01(fmaf(cf, r,  cm));
        g  = clip01(fmaf(cf, g,  cm));
        bl = clip01(fmaf(cf, bl, cm));
        float gray = 0.299f * r + 0.587f * g + 0.114f * bl;
        float sm = (1.0f - sf) * gray;
        r  = clip01(fmaf(sf, r,  sm));
        g  = clip01(fmaf(sf, g,  sm));
        bl = clip01(fmaf(sf, bl, sm));

        // HSV hue rotation:  v*s = cr,  v*(1-s) = minc  ->  ch = minc + cr*w_ch
        float maxc = fmaxf(r, fmaxf(g, bl));
        float minc = fminf(r, fminf(g, bl));
        float cr   = maxc - minc;
        float crd  = (cr == 0.0f) ? 1.0f : cr;
        float inv6 = rcp_approx(crd) * (1.0f / 6.0f);

        bool pr = (maxc == r);
        bool pg = (maxc == g) && !pr;
        float da   = pr ? g  : (pg ? bl : r);
        float db   = pr ? bl : (pg ? r  : g);
        float off6 = pr ? 0.0f : (pg ? (2.0f / 6.0f) : (4.0f / 6.0f));
        float hbase = fmaf(da - db, inv6, off6);

        R.v[k]  = hsv_ch(hbase + hk_r, cr, minc);
        G.v[k]  = hsv_ch(hbase + hk_g, cr, minc);
        Bv.v[k] = hsv_ch(hbase + hk_b, cr, minc);
    }

    st8_cs(obase,          R.v);
    st8_cs(obase + HW,     G.v);
    st8_cs(obase + 2 * HW, Bv.v);
}

extern "C" void kernel_launch(void* const* d_in, const int* in_sizes, int n_in,
                              void* d_out, int out_size) {
    const float* x  = (const float*)d_in[0];
    const float* bf = (const float*)d_in[1];
    const float* cf = (const float*)d_in[2];
    const float* sf = (const float*)d_in[3];
    const float* hf = (const float*)d_in[4];
    float* out = (float*)d_out;

    gray_reduce<<<dim3(PBLK, Bsz), TPB>>>(x, bf);
    color_xform<<<Bsz * PBLK, TPB>>>(x, bf, cf, sf, hf, out);
}